// round 1
// baseline (speedup 1.0000x reference)
#include <cuda_runtime.h>
#include <math.h>

// ---------------------------------------------------------------------------
// PhasePicker: 5x (dilated reflect-pad conv1d K=5 -> BN(eval) -> ReLU -> up2)
// final stage: conv + bias -> up2 -> transpose to [BT,3,NT_OUT,ST]
// plus masked cross-entropy loss scalar.
// B = BT*ST = 256 independent rows.
// ---------------------------------------------------------------------------

#define BATCH 256
#define NT0   1024
#define NT_OUT 32768
#define OUT_ELEMS (32u * 3u * 32768u * 8u)   // 25,165,824

// scratch ping-pong buffers (134 MB each) — __device__ globals, no allocs
__device__ float g_bufA[BATCH * 64 * 2048];
__device__ float g_bufB[BATCH * 64 * 2048];
__device__ double g_loss_accum;
__device__ int    g_mask[BATCH];

// ---------------------------------------------------------------------------
// Fused conv(dilated, reflect) + BN/bias + ReLU + linear x2 upsample.
// One block: one batch row, TL output positions (pre-upsample).
// Register tile: RC couts x RL positions per thread; 256 threads/block.
// ---------------------------------------------------------------------------
template<int CIN, int COUT, int DIL, int TL, int RC, int RL, bool BN, bool FINAL>
__global__ __launch_bounds__(256)
void conv_layer(const float* __restrict__ x,   // [B, CIN, L]
                const float* __restrict__ w,   // [COUT, CIN, 5]
                const float* __restrict__ gg,
                const float* __restrict__ bb,
                const float* __restrict__ mm,
                const float* __restrict__ vv,
                const float* __restrict__ bout, // [3] final bias
                float* __restrict__ y,          // [B, COUT, 2L]  or d_out (FINAL)
                int L)
{
    constexpr int PAD   = 2 * DIL;
    constexpr int HALO  = TL + 4 * DIL + 2;     // extra +-1 for upsample edges
    constexpr int CHUNK = (CIN < 16) ? CIN : 16;
    constexpr int NPG   = TL / RL;

    const int tid  = threadIdx.x;
    const int tile = blockIdx.x;
    const int b    = blockIdx.y;
    const int base = tile * TL - PAD - 1;

    extern __shared__ float sm[];
    float* Xs = sm;                              // CIN * HALO
    float* Ws = Xs + CIN * HALO;                 // COUT * CHUNK * 5
    float* Ys = Ws + COUT * CHUNK * 5;           // COUT * (TL+2)

    // ---- load input tile with reflect padding ----
    const float* xb = x + (size_t)b * CIN * L;
    for (int idx = tid; idx < CIN * HALO; idx += 256) {
        int cin = idx / HALO;
        int j   = idx - cin * HALO;
        int gi  = base + j;
        if (gi < 0)  gi = -gi;
        if (gi >= L) gi = 2 * L - 2 - gi;
        Xs[idx] = xb[cin * L + gi];
    }

    float acc[RC][RL];
#pragma unroll
    for (int q = 0; q < RC; q++)
#pragma unroll
        for (int r = 0; r < RL; r++) acc[q][r] = 0.f;

    const int pg = tid % NPG;
    const int cg = tid / NPG;
    const int lb = pg * RL;
    const int cb = cg * RC;

    // ---- main conv accumulation, W staged per cin-chunk ----
    for (int cc = 0; cc < CIN; cc += CHUNK) {
        __syncthreads();
        for (int idx = tid; idx < COUT * CHUNK * 5; idx += 256) {
            int co = idx / (CHUNK * 5);
            int r  = idx - co * (CHUNK * 5);
            int ci = r / 5;
            int k  = r - ci * 5;
            Ws[idx] = w[(co * CIN + cc + ci) * 5 + k];
        }
        __syncthreads();
#pragma unroll 2
        for (int ci = 0; ci < CHUNK; ci++) {
            const float* xr = Xs + (cc + ci) * HALO + lb + 1;
#pragma unroll
            for (int k = 0; k < 5; k++) {
                float bv[RL];
#pragma unroll
                for (int r = 0; r < RL; r++) bv[r] = xr[r + k * DIL];
#pragma unroll
                for (int q = 0; q < RC; q++) {
                    float wv = Ws[(cb + q) * (CHUNK * 5) + ci * 5 + k];
#pragma unroll
                    for (int r = 0; r < RL; r++)
                        acc[q][r] = fmaf(wv, bv[r], acc[q][r]);
                }
            }
        }
    }

    // ---- BN/bias (+ReLU) -> Ys interior ----
#pragma unroll
    for (int q = 0; q < RC; q++) {
        int c = cb + q;
        float sc, sh;
        if (FINAL) { sc = 1.f; sh = bout[c]; }
        else {
            float inv = gg[c] * rsqrtf(vv[c] + 1e-5f);
            sc = inv; sh = bb[c] - mm[c] * inv;
        }
#pragma unroll
        for (int r = 0; r < RL; r++) {
            float val = acc[q][r] * sc + sh;
            if (BN) val = fmaxf(val, 0.f);
            Ys[c * (TL + 2) + lb + r + 1] = val;
        }
    }

    // ---- tile-edge conv values (for upsample neighbors), clamped at seq ends
    if (tid < 2 * COUT) {
        int co = tid >> 1;
        int e  = tid & 1;
        int gl = tile * TL + (e ? TL : -1);
        if (gl < 0)  gl = 0;
        if (gl >= L) gl = L - 1;
        int lcl = gl - tile * TL;
        float s = 0.f;
        for (int ci2 = 0; ci2 < CIN; ci2++) {
#pragma unroll
            for (int k = 0; k < 5; k++)
                s = fmaf(__ldg(&w[(co * CIN + ci2) * 5 + k]),
                         Xs[ci2 * HALO + lcl + 1 + k * DIL], s);
        }
        float val;
        if (FINAL) val = s + bout[co];
        else {
            float inv = gg[co] * rsqrtf(vv[co] + 1e-5f);
            val = s * inv + bb[co] - mm[co] * inv;
            val = fmaxf(val, 0.f);
        }
        Ys[co * (TL + 2) + (e ? TL + 1 : 0)] = val;
    }
    __syncthreads();

    // ---- linear x2 upsample + store ----
    const int Lup = 2 * L;
#pragma unroll
    for (int q = 0; q < RC; q++) {
        int c = cb + q;
        const float* yr = Ys + c * (TL + 2);
#pragma unroll
        for (int r = 0; r < RL; r++) {
            int j = lb + r;
            float ym = yr[j], y0 = yr[j + 1], yp = yr[j + 2];
            float o0 = 0.25f * ym + 0.75f * y0;
            float o1 = 0.75f * y0 + 0.25f * yp;
            int t = 2 * (tile * TL + j);
            if (FINAL) {
                // out[bt][c][t][st], b = bt*8 + st
                int bt = b >> 3, st = b & 7;
                size_t addr = (((size_t)(bt * 3 + c) * Lup) + t) * 8 + st;
                y[addr]     = o0;
                y[addr + 8] = o1;
            } else {
                float2 o2 = make_float2(o0, o1);
                *reinterpret_cast<float2*>(y + ((size_t)b * COUT + c) * Lup + t) = o2;
            }
        }
    }
}

// ---------------------------------------------------------------------------
// Loss: sum over all (bt,c,t,st) of targets*(lse - out), plus nonzero mask
// per (bt,st). Coalesced over flattened f = t*8+st.
// ---------------------------------------------------------------------------
__global__ __launch_bounds__(256)
void loss_kernel(const float* __restrict__ out, const float* __restrict__ tg,
                 double* accum, int* mask)
{
    const int bt   = blockIdx.y;
    const int chnk = blockIdx.x;     // 64 chunks x 4096 flat elems
    const int tid  = threadIdx.x;
    const size_t base = (size_t)bt * 3 * NT_OUT * 8;
    const size_t chstride = (size_t)NT_OUT * 8;

    float s = 0.f;
    bool nz = false;
#pragma unroll 4
    for (int i = 0; i < 16; i++) {
        size_t f  = (size_t)chnk * 4096 + tid + i * 256;
        size_t a0 = base + f;
        float o0 = out[a0], o1 = out[a0 + chstride], o2 = out[a0 + 2 * chstride];
        float t0 = tg[a0],  t1 = tg[a0 + chstride],  t2 = tg[a0 + 2 * chstride];
        float mx  = fmaxf(o0, fmaxf(o1, o2));
        float lse = mx + logf(expf(o0 - mx) + expf(o1 - mx) + expf(o2 - mx));
        s += t0 * (lse - o0) + t1 * (lse - o1) + t2 * (lse - o2);
        nz = nz || (t0 != 0.f) || (t1 != 0.f) || (t2 != 0.f);
    }
    if (nz) atomicOr(&mask[bt * 8 + (tid & 7)], 1);

    __shared__ float red[256];
    red[tid] = s;
    __syncthreads();
    for (int off = 128; off > 0; off >>= 1) {
        if (tid < off) red[tid] += red[tid + off];
        __syncthreads();
    }
    if (tid == 0) atomicAdd(accum, (double)red[0]);
}

__global__ void init_kernel(double* accum, int* mask)
{
    if (threadIdx.x == 0) *accum = 0.0;
    if (threadIdx.x < BATCH) mask[threadIdx.x] = 0;
}

__global__ void finalize_kernel(const double* accum, const int* mask,
                                float* out, int out_size)
{
    if (threadIdx.x != 0 || blockIdx.x != 0) return;
    int num = 0;
    for (int i = 0; i < BATCH; i++) num += (mask[i] ? 1 : 0);
    double loss = *accum / ((double)num * (double)NT_OUT);
    if ((unsigned)out_size > OUT_ELEMS) out[OUT_ELEMS] = (float)loss;
}

// ---------------------------------------------------------------------------
// Launch
// ---------------------------------------------------------------------------
static constexpr int smem_bytes(int CIN, int COUT, int DIL, int TL) {
    int chunk = (CIN < 16) ? CIN : 16;
    return (CIN * (TL + 4 * DIL + 2) + COUT * chunk * 5 + COUT * (TL + 2)) * 4;
}

extern "C" void kernel_launch(void* const* d_in, const int* in_sizes, int n_in,
                              void* d_out, int out_size)
{
    const float* x  = (const float*)d_in[0];
    const float* tg = (const float*)d_in[1];
    const float *w[5], *g[4], *bb[4], *mm[4], *vv[4], *b_out;

    // metadata order: interleaved (w0,g0,b0,m0,v0, w1, ...) if in_sizes[3]==64
    bool inter = (n_in > 3) && (in_sizes[3] == 64);
    if (inter) {
        for (int i = 0; i < 4; i++) {
            w[i]  = (const float*)d_in[2 + 5 * i];
            g[i]  = (const float*)d_in[3 + 5 * i];
            bb[i] = (const float*)d_in[4 + 5 * i];
            mm[i] = (const float*)d_in[5 + 5 * i];
            vv[i] = (const float*)d_in[6 + 5 * i];
        }
    } else {
        for (int i = 0; i < 4; i++) {
            w[i]  = (const float*)d_in[2 + i];
            g[i]  = (const float*)d_in[6 + i];
            bb[i] = (const float*)d_in[10 + i];
            mm[i] = (const float*)d_in[14 + i];
            vv[i] = (const float*)d_in[18 + i];
        }
    }
    w[4]  = (const float*)d_in[22];
    b_out = (const float*)d_in[23];

    float *bufA, *bufB;
    double* accum;
    int* mask;
    cudaGetSymbolAddress((void**)&bufA, g_bufA);
    cudaGetSymbolAddress((void**)&bufB, g_bufB);
    cudaGetSymbolAddress((void**)&accum, g_loss_accum);
    cudaGetSymbolAddress((void**)&mask, g_mask);

    constexpr int SM0 = smem_bytes(128, 64, 1, 64);
    constexpr int SM1 = smem_bytes(64, 32, 2, 128);
    constexpr int SM2 = smem_bytes(32, 16, 4, 256);
    constexpr int SM3 = smem_bytes(16, 8, 8, 512);
    constexpr int SM4 = smem_bytes(8, 3, 16, 1024);

    cudaFuncSetAttribute(conv_layer<128, 64, 1, 64, 4, 4, true, false>,
                         cudaFuncAttributeMaxDynamicSharedMemorySize, SM0);
    cudaFuncSetAttribute(conv_layer<64, 32, 2, 128, 4, 4, true, false>,
                         cudaFuncAttributeMaxDynamicSharedMemorySize, SM1);
    cudaFuncSetAttribute(conv_layer<32, 16, 4, 256, 4, 4, true, false>,
                         cudaFuncAttributeMaxDynamicSharedMemorySize, SM2);
    cudaFuncSetAttribute(conv_layer<16, 8, 8, 512, 4, 4, true, false>,
                         cudaFuncAttributeMaxDynamicSharedMemorySize, SM3);
    cudaFuncSetAttribute(conv_layer<8, 3, 16, 1024, 3, 4, false, true>,
                         cudaFuncAttributeMaxDynamicSharedMemorySize, SM4);

    init_kernel<<<1, 256>>>(accum, mask);

    conv_layer<128, 64, 1, 64, 4, 4, true, false>
        <<<dim3(1024 / 64, BATCH), 256, SM0>>>(x, w[0], g[0], bb[0], mm[0], vv[0],
                                               nullptr, bufA, 1024);
    conv_layer<64, 32, 2, 128, 4, 4, true, false>
        <<<dim3(2048 / 128, BATCH), 256, SM1>>>(bufA, w[1], g[1], bb[1], mm[1], vv[1],
                                                nullptr, bufB, 2048);
    conv_layer<32, 16, 4, 256, 4, 4, true, false>
        <<<dim3(4096 / 256, BATCH), 256, SM2>>>(bufB, w[2], g[2], bb[2], mm[2], vv[2],
                                                nullptr, bufA, 4096);
    conv_layer<16, 8, 8, 512, 4, 4, true, false>
        <<<dim3(8192 / 512, BATCH), 256, SM3>>>(bufA, w[3], g[3], bb[3], mm[3], vv[3],
                                                nullptr, bufB, 8192);
    conv_layer<8, 3, 16, 1024, 3, 4, false, true>
        <<<dim3(16384 / 1024, BATCH), 256, SM4>>>(bufB, w[4], nullptr, nullptr, nullptr,
                                                  nullptr, b_out, (float*)d_out, 16384);

    loss_kernel<<<dim3(64, 32), 256>>>((const float*)d_out, tg, accum, mask);
    finalize_kernel<<<1, 1>>>(accum, mask, (float*)d_out, out_size);
}

// round 2
// speedup vs baseline: 1.7929x; 1.7929x over previous
#include <cuda_runtime.h>
#include <math.h>

#define BATCH 256
#define NT_OUT 32768
#define OUT_ELEMS (32u * 3u * 32768u * 8u)   // 25,165,824

// scratch ping-pong buffers — __device__ globals, no allocs
__device__ float g_bufA[BATCH * 64 * 2048];
__device__ float g_bufB[BATCH * 64 * 2048];
__device__ double g_loss_accum;
__device__ int    g_mask[BATCH];

typedef unsigned long long u64;

__device__ __forceinline__ void fma2(u64 &d, u64 a, u64 b) {
    asm("fma.rn.f32x2 %0, %1, %2, %0;" : "+l"(d) : "l"(a), "l"(b));
}
__device__ __forceinline__ u64 pack2(float lo, float hi) {
    u64 r; asm("mov.b64 %0, {%1, %2};" : "=l"(r) : "f"(lo), "f"(hi)); return r;
}
__device__ __forceinline__ void unpack2(u64 v, float &lo, float &hi) {
    asm("mov.b64 {%0, %1}, %2;" : "=f"(lo), "=f"(hi) : "l"(v));
}

// ---------------------------------------------------------------------------
// Fused conv(dilated, reflect) + BN/bias + ReLU + linear x2 upsample.
// Register tile: RC couts x 4 positions per thread, packed f32x2 FMA.
// X tile: vector LDS.128, shifted so inner offsets are 16B aligned.
// W tile: duplicated pairs {w,w} -> broadcast LDS.128, no packing.
// ---------------------------------------------------------------------------
template<int CIN, int COUT, int DIL, int TL, int RC, int CHUNK, bool BN, bool FINAL>
__global__ __launch_bounds__(256, 2)
void conv_layer(const float* __restrict__ x,   // [B, CIN, L]
                const float* __restrict__ w,   // [COUT, CIN, 5]
                const float* __restrict__ gg,
                const float* __restrict__ bb,
                const float* __restrict__ mm,
                const float* __restrict__ vv,
                const float* __restrict__ bout,
                float* __restrict__ y,          // [B, COUT, 2L]
                int L)
{
    constexpr int PAD   = 2 * DIL;
    constexpr int SFT   = PAD + 4;                 // halo shift => aligned inner offsets
    constexpr int HALO  = TL + 2 * PAD + 5;
    constexpr int HALOP = (HALO + 3) & ~3;
    constexpr int NPG   = TL / 4;
    constexpr int CG    = 256 / NPG;
    constexpr int COUTP = (COUT + 3) & ~3;
    constexpr int TLP   = TL + 4;
    constexpr int NQ    = (RC + 1) / 2;

    const int tid  = threadIdx.x;
    const int tile = blockIdx.x;
    const int b    = blockIdx.y;
    const int pg   = tid % NPG;
    const int cg   = tid / NPG;
    const int lb   = pg * 4;
    const int cb   = cg * RC;

    extern __shared__ float sm[];
    float* Xs  = sm;                               // CHUNK * HALOP
    float* Ws  = Xs + CHUNK * HALOP;               // CHUNK * 5 * 2 * COUTP (dup pairs)
    float* Ys  = Ws + CHUNK * 10 * COUTP;          // COUT * TLP (interior)
    float* YsE = Ys + COUT * TLP;                  // COUT * 2 (tile-edge values)

    const float* xb  = x + (size_t)b * CIN * L;
    const int    gbase = tile * TL - SFT;

    u64 acc[RC][2];
#pragma unroll
    for (int q = 0; q < RC; q++) { acc[q][0] = 0ull; acc[q][1] = 0ull; }

    // tile-edge (upsample neighbor) accumulators
    float eacc = 0.f;
    const int eIdx = tid >> 1, eSide = tid & 1;
    int ej = 0;
    if (tid < 2 * COUT) {
        int gl = tile * TL + (eSide ? TL : -1);
        if (gl < 0)  gl = 0;
        if (gl >= L) gl = L - 1;
        ej = gl - tile * TL;
    }

    for (int cc = 0; cc < CIN; cc += CHUNK) {
        __syncthreads();
        // ---- stage X chunk with reflect padding ----
        for (int idx = tid; idx < CHUNK * HALO; idx += 256) {
            int ci = idx / HALO, j = idx - ci * HALO;
            int gi = gbase + j;
            if (gi < 0)  gi = -gi;
            if (gi >= L) gi = 2 * L - 2 - gi;
            Xs[ci * HALOP + j] = xb[(cc + ci) * L + gi];
        }
        // ---- stage W chunk, duplicated pairs, [ci][k][2*co] ----
        for (int idx = tid; idx < COUT * CHUNK * 5; idx += 256) {
            int co = idx / (CHUNK * 5), r = idx - co * (CHUNK * 5);
            int ci = r / 5, k = r - ci * 5;
            float v = w[(co * CIN + cc + ci) * 5 + k];
            int o = (ci * 5 + k) * 2 * COUTP + 2 * co;
            Ws[o] = v; Ws[o + 1] = v;
        }
        __syncthreads();

#pragma unroll 1
        for (int ci = 0; ci < CHUNK; ci++) {
            const float* xr = Xs + ci * HALOP + lb + 4;
            if (DIL == 1) {
                float4 f0 = *(const float4*)xr;
                float4 f1 = *(const float4*)(xr + 4);
                float fv[8] = {f0.x, f0.y, f0.z, f0.w, f1.x, f1.y, f1.z, f1.w};
                u64 P[7];
#pragma unroll
                for (int i = 0; i < 7; i++) P[i] = pack2(fv[i], fv[i + 1]);
#pragma unroll
                for (int k = 0; k < 5; k++) {
                    u64 xp0 = P[k], xp1 = P[k + 2];
                    const float* wr = Ws + (ci * 5 + k) * 2 * COUTP + 2 * cb;
#pragma unroll
                    for (int qq = 0; qq < NQ; qq++) {
                        ulonglong2 wv = *(const ulonglong2*)(wr + 4 * qq);
                        fma2(acc[2 * qq][0], wv.x, xp0);
                        fma2(acc[2 * qq][1], wv.x, xp1);
                        if (2 * qq + 1 < RC) {
                            fma2(acc[2 * qq + 1][0], wv.y, xp0);
                            fma2(acc[2 * qq + 1][1], wv.y, xp1);
                        }
                    }
                }
            } else if (DIL == 2) {
                ulonglong2 e0 = *(const ulonglong2*)xr;
                ulonglong2 e1 = *(const ulonglong2*)(xr + 4);
                ulonglong2 e2 = *(const ulonglong2*)(xr + 8);
                u64 E[6] = {e0.x, e0.y, e1.x, e1.y, e2.x, e2.y};
#pragma unroll
                for (int k = 0; k < 5; k++) {
                    u64 xp0 = E[k], xp1 = E[k + 1];
                    const float* wr = Ws + (ci * 5 + k) * 2 * COUTP + 2 * cb;
#pragma unroll
                    for (int qq = 0; qq < NQ; qq++) {
                        ulonglong2 wv = *(const ulonglong2*)(wr + 4 * qq);
                        fma2(acc[2 * qq][0], wv.x, xp0);
                        fma2(acc[2 * qq][1], wv.x, xp1);
                        if (2 * qq + 1 < RC) {
                            fma2(acc[2 * qq + 1][0], wv.y, xp0);
                            fma2(acc[2 * qq + 1][1], wv.y, xp1);
                        }
                    }
                }
            } else {
#pragma unroll
                for (int k = 0; k < 5; k++) {
                    ulonglong2 xv = *(const ulonglong2*)(xr + k * DIL);
                    u64 xp0 = xv.x, xp1 = xv.y;
                    const float* wr = Ws + (ci * 5 + k) * 2 * COUTP + 2 * cb;
#pragma unroll
                    for (int qq = 0; qq < NQ; qq++) {
                        ulonglong2 wv = *(const ulonglong2*)(wr + 4 * qq);
                        fma2(acc[2 * qq][0], wv.x, xp0);
                        fma2(acc[2 * qq][1], wv.x, xp1);
                        if (2 * qq + 1 < RC) {
                            fma2(acc[2 * qq + 1][0], wv.y, xp0);
                            fma2(acc[2 * qq + 1][1], wv.y, xp1);
                        }
                    }
                }
            }
        }

        // ---- tile-edge accumulation over this chunk ----
        if (tid < 2 * COUT) {
#pragma unroll 1
            for (int ci = 0; ci < CHUNK; ci++)
#pragma unroll
                for (int k = 0; k < 5; k++)
                    eacc = fmaf(Ws[(ci * 5 + k) * 2 * COUTP + 2 * eIdx],
                                Xs[ci * HALOP + ej + 4 + k * DIL], eacc);
        }
    }

    // ---- BN/bias (+ReLU), store interior to Ys (aligned float4) ----
#pragma unroll
    for (int q = 0; q < RC; q++) {
        int c = cb + q;
        float sc, sh;
        if (FINAL) { sc = 1.f; sh = bout[c]; }
        else {
            float inv = gg[c] * rsqrtf(vv[c] + 1e-5f);
            sc = inv; sh = bb[c] - mm[c] * inv;
        }
        float a0, a1, a2, a3;
        unpack2(acc[q][0], a0, a1);
        unpack2(acc[q][1], a2, a3);
        a0 = a0 * sc + sh; a1 = a1 * sc + sh;
        a2 = a2 * sc + sh; a3 = a3 * sc + sh;
        if (BN) {
            a0 = fmaxf(a0, 0.f); a1 = fmaxf(a1, 0.f);
            a2 = fmaxf(a2, 0.f); a3 = fmaxf(a3, 0.f);
        }
        *(float4*)(Ys + c * TLP + lb) = make_float4(a0, a1, a2, a3);
    }
    if (tid < 2 * COUT) {
        int c = eIdx;
        float sc, sh;
        if (FINAL) { sc = 1.f; sh = bout[c]; }
        else {
            float inv = gg[c] * rsqrtf(vv[c] + 1e-5f);
            sc = inv; sh = bb[c] - mm[c] * inv;
        }
        float v = eacc * sc + sh;
        if (BN) v = fmaxf(v, 0.f);
        YsE[2 * c + eSide] = v;
    }
    __syncthreads();

    // ---- linear x2 upsample + coalesced store ----
    const int Lup = 2 * L;
#pragma unroll
    for (int q = 0; q < RC; q++) {
        int c = cb + q;
        const float* row = Ys + c * TLP;
        float4 y4 = *(const float4*)(row + lb);
        float yl = lb ? row[lb - 1] : YsE[2 * c];
        float yr = (lb == TL - 4) ? YsE[2 * c + 1] : row[lb + 4];
        float o0 = 0.25f * yl   + 0.75f * y4.x, o1 = 0.75f * y4.x + 0.25f * y4.y;
        float o2 = 0.25f * y4.x + 0.75f * y4.y, o3 = 0.75f * y4.y + 0.25f * y4.z;
        float o4 = 0.25f * y4.y + 0.75f * y4.z, o5 = 0.75f * y4.z + 0.25f * y4.w;
        float o6 = 0.25f * y4.z + 0.75f * y4.w, o7 = 0.75f * y4.w + 0.25f * yr;
        size_t off = ((size_t)b * COUT + c) * Lup + 2 * (tile * TL + lb);
        *(float4*)(y + off)     = make_float4(o0, o1, o2, o3);
        *(float4*)(y + off + 4) = make_float4(o4, o5, o6, o7);
    }
}

// ---------------------------------------------------------------------------
// Transpose [b=bt*8+st][3][T] -> [bt][3][T][st] through shared tile, fused
// with masked cross-entropy loss. All reads/writes coalesced, bank-free.
// ---------------------------------------------------------------------------
#define TT 512
#define TTP 516   // row pad: bank-conflict-free transpose reads
__global__ __launch_bounds__(256)
void transpose_loss(const float* __restrict__ in, const float* __restrict__ tg,
                    float* __restrict__ out, double* accum, int* mask)
{
    const int bt = blockIdx.y;
    const int t0 = blockIdx.x * TT;
    const int tid = threadIdx.x;
    extern __shared__ float tile[];               // [3][8][TTP]

    for (int idx = tid; idx < 3 * 8 * TT; idx += 256) {
        int c = idx / (8 * TT), r = idx - c * (8 * TT);
        int st = r / TT, t = r - st * TT;
        tile[(c * 8 + st) * TTP + t] =
            in[((size_t)(bt * 8 + st) * 3 + c) * NT_OUT + t0 + t];
    }
    __syncthreads();

    float s = 0.f;
    bool nz = false;
    const size_t ob = ((size_t)bt * 3) * NT_OUT * 8 + (size_t)t0 * 8;
    const size_t cs = (size_t)NT_OUT * 8;
#pragma unroll 4
    for (int i = 0; i < (TT * 8) / 256; i++) {
        int f = i * 256 + tid;
        int t = f >> 3, st = f & 7;
        float o0 = tile[(0 * 8 + st) * TTP + t];
        float o1 = tile[(1 * 8 + st) * TTP + t];
        float o2 = tile[(2 * 8 + st) * TTP + t];
        out[ob + f]          = o0;
        out[ob + cs + f]     = o1;
        out[ob + 2 * cs + f] = o2;
        float t0v = tg[ob + f], t1v = tg[ob + cs + f], t2v = tg[ob + 2 * cs + f];
        float mx  = fmaxf(o0, fmaxf(o1, o2));
        float lse = mx + __logf(__expf(o0 - mx) + __expf(o1 - mx) + __expf(o2 - mx));
        s += t0v * (lse - o0) + t1v * (lse - o1) + t2v * (lse - o2);
        nz = nz || (t0v != 0.f) || (t1v != 0.f) || (t2v != 0.f);
    }
    if (nz) atomicOr(&mask[bt * 8 + (tid & 7)], 1);

    __shared__ float red[256];
    red[tid] = s;
    __syncthreads();
    for (int o = 128; o > 0; o >>= 1) {
        if (tid < o) red[tid] += red[tid + o];
        __syncthreads();
    }
    if (tid == 0) atomicAdd(accum, (double)red[0]);
}

__global__ void init_kernel(double* accum, int* mask)
{
    if (threadIdx.x == 0) *accum = 0.0;
    if (threadIdx.x < BATCH) mask[threadIdx.x] = 0;
}

__global__ void finalize_kernel(const double* accum, const int* mask,
                                float* out, int out_size)
{
    if (threadIdx.x != 0 || blockIdx.x != 0) return;
    int num = 0;
    for (int i = 0; i < BATCH; i++) num += (mask[i] ? 1 : 0);
    double loss = *accum / ((double)num * (double)NT_OUT);
    if ((unsigned)out_size > OUT_ELEMS) out[OUT_ELEMS] = (float)loss;
}

// ---------------------------------------------------------------------------
// Launch
// ---------------------------------------------------------------------------
static constexpr int conv_smem(int CIN, int COUT, int DIL, int TL, int CHUNK) {
    int halop = ((TL + 4 * DIL + 5) + 3) & ~3;
    int coutp = (COUT + 3) & ~3;
    return (CHUNK * halop + CHUNK * 10 * coutp + COUT * (TL + 4) + COUT * 2) * 4;
}

extern "C" void kernel_launch(void* const* d_in, const int* in_sizes, int n_in,
                              void* d_out, int out_size)
{
    const float* x  = (const float*)d_in[0];
    const float* tg = (const float*)d_in[1];
    const float *w[5], *g[4], *bb[4], *mm[4], *vv[4], *b_out;

    bool inter = (n_in > 3) && (in_sizes[3] == 64);
    if (inter) {
        for (int i = 0; i < 4; i++) {
            w[i]  = (const float*)d_in[2 + 5 * i];
            g[i]  = (const float*)d_in[3 + 5 * i];
            bb[i] = (const float*)d_in[4 + 5 * i];
            mm[i] = (const float*)d_in[5 + 5 * i];
            vv[i] = (const float*)d_in[6 + 5 * i];
        }
    } else {
        for (int i = 0; i < 4; i++) {
            w[i]  = (const float*)d_in[2 + i];
            g[i]  = (const float*)d_in[6 + i];
            bb[i] = (const float*)d_in[10 + i];
            mm[i] = (const float*)d_in[14 + i];
            vv[i] = (const float*)d_in[18 + i];
        }
    }
    w[4]  = (const float*)d_in[22];
    b_out = (const float*)d_in[23];

    float *bufA, *bufB;
    double* accum;
    int* mask;
    cudaGetSymbolAddress((void**)&bufA, g_bufA);
    cudaGetSymbolAddress((void**)&bufB, g_bufB);
    cudaGetSymbolAddress((void**)&accum, g_loss_accum);
    cudaGetSymbolAddress((void**)&mask, g_mask);

    constexpr int SM0 = conv_smem(128, 64, 1, 128, 8);
    constexpr int SM1 = conv_smem(64, 32, 2, 256, 8);
    constexpr int SM2 = conv_smem(32, 16, 4, 512, 8);
    constexpr int SM3 = conv_smem(16, 8, 8, 1024, 8);
    constexpr int SM4 = conv_smem(8, 3, 16, 1024, 8);
    constexpr int SMT = 3 * 8 * TTP * 4;

    cudaFuncSetAttribute(conv_layer<128, 64, 1, 128, 8, 8, true, false>,
                         cudaFuncAttributeMaxDynamicSharedMemorySize, SM0);
    cudaFuncSetAttribute(conv_layer<64, 32, 2, 256, 8, 8, true, false>,
                         cudaFuncAttributeMaxDynamicSharedMemorySize, SM1);
    cudaFuncSetAttribute(conv_layer<32, 16, 4, 512, 8, 8, true, false>,
                         cudaFuncAttributeMaxDynamicSharedMemorySize, SM2);
    cudaFuncSetAttribute(conv_layer<16, 8, 8, 1024, 8, 8, true, false>,
                         cudaFuncAttributeMaxDynamicSharedMemorySize, SM3);
    cudaFuncSetAttribute(conv_layer<8, 3, 16, 1024, 3, 8, false, true>,
                         cudaFuncAttributeMaxDynamicSharedMemorySize, SM4);
    cudaFuncSetAttribute(transpose_loss,
                         cudaFuncAttributeMaxDynamicSharedMemorySize, SMT);

    init_kernel<<<1, 256>>>(accum, mask);

    conv_layer<128, 64, 1, 128, 8, 8, true, false>
        <<<dim3(1024 / 128, BATCH), 256, SM0>>>(x, w[0], g[0], bb[0], mm[0], vv[0],
                                                nullptr, bufA, 1024);
    conv_layer<64, 32, 2, 256, 8, 8, true, false>
        <<<dim3(2048 / 256, BATCH), 256, SM1>>>(bufA, w[1], g[1], bb[1], mm[1], vv[1],
                                                nullptr, bufB, 2048);
    conv_layer<32, 16, 4, 512, 8, 8, true, false>
        <<<dim3(4096 / 512, BATCH), 256, SM2>>>(bufB, w[2], g[2], bb[2], mm[2], vv[2],
                                                nullptr, bufA, 4096);
    conv_layer<16, 8, 8, 1024, 8, 8, true, false>
        <<<dim3(8192 / 1024, BATCH), 256, SM3>>>(bufA, w[3], g[3], bb[3], mm[3], vv[3],
                                                 nullptr, bufB, 8192);
    conv_layer<8, 3, 16, 1024, 3, 8, false, true>
        <<<dim3(16384 / 1024, BATCH), 256, SM4>>>(bufB, w[4], nullptr, nullptr, nullptr,
                                                  nullptr, b_out, bufA, 16384);

    transpose_loss<<<dim3(NT_OUT / TT, 32), 256, SMT>>>(bufA, tg, (float*)d_out,
                                                        accum, mask);
    finalize_kernel<<<1, 1>>>(accum, mask, (float*)d_out, out_size);
}

// round 3
// speedup vs baseline: 1.9377x; 1.0808x over previous
#include <cuda_runtime.h>
#include <math.h>

#define BATCH 256
#define NT_OUT 32768
#define OUT_ELEMS (32u * 3u * 32768u * 8u)   // 25,165,824

// scratch — __device__ globals, no allocs
__device__ float g_bufA[BATCH * 64 * 2048];
__device__ float g_bufB[BATCH * 64 * 2048];
__device__ float g_wprep[131072];
__device__ double g_loss_accum;
__device__ int    g_mask[BATCH];

typedef unsigned long long u64;

__device__ __forceinline__ void fma2(u64 &d, u64 a, u64 b) {
    asm("fma.rn.f32x2 %0, %1, %2, %0;" : "+l"(d) : "l"(a), "l"(b));
}
__device__ __forceinline__ u64 pack2(float lo, float hi) {
    u64 r; asm("mov.b64 %0, {%1, %2};" : "=l"(r) : "f"(lo), "f"(hi)); return r;
}
__device__ __forceinline__ void unpack2(u64 v, float &lo, float &hi) {
    asm("mov.b64 {%0, %1}, %2;" : "=f"(lo), "=f"(hi) : "l"(v));
}
__device__ __forceinline__ unsigned sm_u32(const void* p) {
    unsigned a;
    asm("{.reg .u64 t; cvta.to.shared.u64 t, %1; cvt.u32.u64 %0, t;}"
        : "=r"(a) : "l"(p));
    return a;
}

// ---------------------------------------------------------------------------
// Weight pre-format: [COUT][CIN][5] -> per-chunk [ci][k][{w,w} x co] dup pairs
// ---------------------------------------------------------------------------
__global__ void prep_weights(const float* __restrict__ w, float* __restrict__ dst,
                             int CIN, int COUT, int COUTP, int CHUNK)
{
    int idx = blockIdx.x * 256 + threadIdx.x;
    int n = COUT * CIN * 5;
    if (idx >= n) return;
    int co = idx / (CIN * 5), r = idx - co * (CIN * 5);
    int ci = r / 5, k = r - ci * 5;
    int q = ci / CHUNK, cil = ci - q * CHUNK;
    float v = w[idx];
    int o = q * (CHUNK * 10 * COUTP) + (cil * 5 + k) * 2 * COUTP + 2 * co;
    dst[o] = v; dst[o + 1] = v;
}

// ---------------------------------------------------------------------------
// Fused conv(dilated, reflect) + BN/bias + ReLU + linear x2 upsample.
// cp.async double-buffered chunk staging; packed f32x2 FMA math.
// ---------------------------------------------------------------------------
template<int CIN, int COUT, int DIL, int TL, int RC, int CHUNK, bool BN, bool FINAL>
__global__ __launch_bounds__(256, 2)
void conv_layer(const float* __restrict__ x,   // [B, CIN, L]
                const float* __restrict__ wp,  // prepped weights
                const float* __restrict__ gg,
                const float* __restrict__ bb,
                const float* __restrict__ mm,
                const float* __restrict__ vv,
                const float* __restrict__ bout,
                float* __restrict__ y,          // [B, COUT, 2L]
                int L)
{
    constexpr int PAD   = 2 * DIL;
    constexpr int SFT   = PAD + 4;
    constexpr int HALO  = TL + 2 * PAD + 5;
    constexpr int HALOP = (HALO + 3) & ~3;
    constexpr int NPG   = TL / 4;
    constexpr int COUTP = (COUT + 3) & ~3;
    constexpr int TLP   = TL + 4;
    constexpr int NQ    = (RC + 1) / 2;
    constexpr int WCH   = CHUNK * 10 * COUTP;
    constexpr int NCH   = CIN / CHUNK;

    const int tid  = threadIdx.x;
    const int tile = blockIdx.x;
    const int b    = blockIdx.y;
    const int pg   = tid % NPG;
    const int cg   = tid / NPG;
    const int lb   = pg * 4;
    const int cb   = cg * RC;

    extern __shared__ float sm[];
    float* Xbuf[2] = { sm, sm + CHUNK * HALOP };
    float* Wbuf[2] = { sm + 2 * CHUNK * HALOP, sm + 2 * CHUNK * HALOP + WCH };
    float* Ys  = sm + 2 * CHUNK * HALOP + 2 * WCH;   // COUT * TLP
    float* YsE = Ys + COUT * TLP;                    // COUT * 2

    const float* xb    = x + (size_t)b * CIN * L;
    const int    gbase = tile * TL - SFT;

    u64 acc[RC][2];
#pragma unroll
    for (int q = 0; q < RC; q++) { acc[q][0] = 0ull; acc[q][1] = 0ull; }

    float eacc = 0.f;
    const int eIdx = tid >> 1, eSide = tid & 1;
    int ej = 0;
    if (tid < 2 * COUT) {
        int gl = tile * TL + (eSide ? TL : -1);
        if (gl < 0)  gl = 0;
        if (gl >= L) gl = L - 1;
        ej = gl - tile * TL;
    }

    // ---- async staging of chunk cc into buffer p ----
    auto stage = [&](int p, int cc) {
        float* Xd = Xbuf[p];
        for (int idx = tid; idx < CHUNK * HALO; idx += 256) {
            int ci = idx / HALO, j = idx - ci * HALO;
            int gi = gbase + j;
            if (gi < 0)  gi = -gi;
            if (gi >= L) gi = 2 * L - 2 - gi;
            unsigned d = sm_u32(Xd + ci * HALOP + j);
            const float* s = xb + (size_t)(cc * CHUNK + ci) * L + gi;
            asm volatile("cp.async.ca.shared.global [%0], [%1], 4;" :: "r"(d), "l"(s));
        }
        const float4* wsrc = (const float4*)(wp + (size_t)cc * WCH);
        float* Wd = Wbuf[p];
        for (int idx = tid; idx < WCH / 4; idx += 256) {
            unsigned d = sm_u32(Wd + idx * 4);
            asm volatile("cp.async.cg.shared.global [%0], [%1], 16;"
                         :: "r"(d), "l"(wsrc + idx));
        }
        asm volatile("cp.async.commit_group;");
    };

    stage(0, 0);

    for (int cc = 0; cc < NCH; cc++) {
        const int p = cc & 1;
        asm volatile("cp.async.wait_group 0;");
        __syncthreads();
        if (cc + 1 < NCH) stage(p ^ 1, cc + 1);

        const float* Xs = Xbuf[p];
        const float* Ws = Wbuf[p];

#pragma unroll 2
        for (int ci = 0; ci < CHUNK; ci++) {
            const float* xr = Xs + ci * HALOP + lb + 4;
            if (DIL == 1) {
                float4 f0 = *(const float4*)xr;
                float4 f1 = *(const float4*)(xr + 4);
                float fv[8] = {f0.x, f0.y, f0.z, f0.w, f1.x, f1.y, f1.z, f1.w};
                u64 P[7];
#pragma unroll
                for (int i = 0; i < 7; i++) P[i] = pack2(fv[i], fv[i + 1]);
#pragma unroll
                for (int k = 0; k < 5; k++) {
                    u64 xp0 = P[k], xp1 = P[k + 2];
                    const float* wr = Ws + (ci * 5 + k) * 2 * COUTP + 2 * cb;
#pragma unroll
                    for (int qq = 0; qq < NQ; qq++) {
                        ulonglong2 wv = *(const ulonglong2*)(wr + 4 * qq);
                        fma2(acc[2 * qq][0], wv.x, xp0);
                        fma2(acc[2 * qq][1], wv.x, xp1);
                        if (2 * qq + 1 < RC) {
                            fma2(acc[2 * qq + 1][0], wv.y, xp0);
                            fma2(acc[2 * qq + 1][1], wv.y, xp1);
                        }
                    }
                }
            } else if (DIL == 2) {
                ulonglong2 e0 = *(const ulonglong2*)xr;
                ulonglong2 e1 = *(const ulonglong2*)(xr + 4);
                ulonglong2 e2 = *(const ulonglong2*)(xr + 8);
                u64 E[6] = {e0.x, e0.y, e1.x, e1.y, e2.x, e2.y};
#pragma unroll
                for (int k = 0; k < 5; k++) {
                    u64 xp0 = E[k], xp1 = E[k + 1];
                    const float* wr = Ws + (ci * 5 + k) * 2 * COUTP + 2 * cb;
#pragma unroll
                    for (int qq = 0; qq < NQ; qq++) {
                        ulonglong2 wv = *(const ulonglong2*)(wr + 4 * qq);
                        fma2(acc[2 * qq][0], wv.x, xp0);
                        fma2(acc[2 * qq][1], wv.x, xp1);
                        if (2 * qq + 1 < RC) {
                            fma2(acc[2 * qq + 1][0], wv.y, xp0);
                            fma2(acc[2 * qq + 1][1], wv.y, xp1);
                        }
                    }
                }
            } else {
#pragma unroll
                for (int k = 0; k < 5; k++) {
                    ulonglong2 xv = *(const ulonglong2*)(xr + k * DIL);
                    u64 xp0 = xv.x, xp1 = xv.y;
                    const float* wr = Ws + (ci * 5 + k) * 2 * COUTP + 2 * cb;
#pragma unroll
                    for (int qq = 0; qq < NQ; qq++) {
                        ulonglong2 wv = *(const ulonglong2*)(wr + 4 * qq);
                        fma2(acc[2 * qq][0], wv.x, xp0);
                        fma2(acc[2 * qq][1], wv.x, xp1);
                        if (2 * qq + 1 < RC) {
                            fma2(acc[2 * qq + 1][0], wv.y, xp0);
                            fma2(acc[2 * qq + 1][1], wv.y, xp1);
                        }
                    }
                }
            }
        }

        if (tid < 2 * COUT) {
#pragma unroll 1
            for (int ci = 0; ci < CHUNK; ci++)
#pragma unroll
                for (int k = 0; k < 5; k++)
                    eacc = fmaf(Ws[(ci * 5 + k) * 2 * COUTP + 2 * eIdx],
                                Xs[ci * HALOP + ej + 4 + k * DIL], eacc);
        }
    }

    // ---- BN/bias (+ReLU) -> Ys ----
#pragma unroll
    for (int q = 0; q < RC; q++) {
        int c = cb + q;
        float sc, sh;
        if (FINAL) { sc = 1.f; sh = bout[c]; }
        else {
            float inv = gg[c] * rsqrtf(vv[c] + 1e-5f);
            sc = inv; sh = bb[c] - mm[c] * inv;
        }
        float a0, a1, a2, a3;
        unpack2(acc[q][0], a0, a1);
        unpack2(acc[q][1], a2, a3);
        a0 = a0 * sc + sh; a1 = a1 * sc + sh;
        a2 = a2 * sc + sh; a3 = a3 * sc + sh;
        if (BN) {
            a0 = fmaxf(a0, 0.f); a1 = fmaxf(a1, 0.f);
            a2 = fmaxf(a2, 0.f); a3 = fmaxf(a3, 0.f);
        }
        *(float4*)(Ys + c * TLP + lb) = make_float4(a0, a1, a2, a3);
    }
    if (tid < 2 * COUT) {
        int c = eIdx;
        float sc, sh;
        if (FINAL) { sc = 1.f; sh = bout[c]; }
        else {
            float inv = gg[c] * rsqrtf(vv[c] + 1e-5f);
            sc = inv; sh = bb[c] - mm[c] * inv;
        }
        float v = eacc * sc + sh;
        if (BN) v = fmaxf(v, 0.f);
        YsE[2 * c + eSide] = v;
    }
    __syncthreads();

    // ---- linear x2 upsample + coalesced store ----
    const int Lup = 2 * L;
#pragma unroll
    for (int q = 0; q < RC; q++) {
        int c = cb + q;
        const float* row = Ys + c * TLP;
        float4 y4 = *(const float4*)(row + lb);
        float yl = lb ? row[lb - 1] : YsE[2 * c];
        float yr = (lb == TL - 4) ? YsE[2 * c + 1] : row[lb + 4];
        float o0 = 0.25f * yl   + 0.75f * y4.x, o1 = 0.75f * y4.x + 0.25f * y4.y;
        float o2 = 0.25f * y4.x + 0.75f * y4.y, o3 = 0.75f * y4.y + 0.25f * y4.z;
        float o4 = 0.25f * y4.y + 0.75f * y4.z, o5 = 0.75f * y4.z + 0.25f * y4.w;
        float o6 = 0.25f * y4.z + 0.75f * y4.w, o7 = 0.75f * y4.w + 0.25f * yr;
        size_t off = ((size_t)b * COUT + c) * Lup + 2 * (tile * TL + lb);
        *(float4*)(y + off)     = make_float4(o0, o1, o2, o3);
        *(float4*)(y + off + 4) = make_float4(o4, o5, o6, o7);
    }
}

// ---------------------------------------------------------------------------
// Transpose [b=bt*8+st][3][T] -> [bt][3][T][st] + fused masked CE loss.
// ---------------------------------------------------------------------------
#define TT 512
#define TTP 516
__global__ __launch_bounds__(256)
void transpose_loss(const float* __restrict__ in, const float* __restrict__ tg,
                    float* __restrict__ out, double* accum, int* mask)
{
    const int bt = blockIdx.y;
    const int t0 = blockIdx.x * TT;
    const int tid = threadIdx.x;
    extern __shared__ float tile[];               // [3][8][TTP]

    for (int idx = tid; idx < 3 * 8 * TT; idx += 256) {
        int c = idx / (8 * TT), r = idx - c * (8 * TT);
        int st = r / TT, t = r - st * TT;
        tile[(c * 8 + st) * TTP + t] =
            in[((size_t)(bt * 8 + st) * 3 + c) * NT_OUT + t0 + t];
    }
    __syncthreads();

    float s = 0.f;
    bool nz = false;
    const size_t ob = ((size_t)bt * 3) * NT_OUT * 8 + (size_t)t0 * 8;
    const size_t cs = (size_t)NT_OUT * 8;
#pragma unroll 4
    for (int i = 0; i < (TT * 8) / 256; i++) {
        int f = i * 256 + tid;
        int t = f >> 3, st = f & 7;
        float o0 = tile[(0 * 8 + st) * TTP + t];
        float o1 = tile[(1 * 8 + st) * TTP + t];
        float o2 = tile[(2 * 8 + st) * TTP + t];
        out[ob + f]          = o0;
        out[ob + cs + f]     = o1;
        out[ob + 2 * cs + f] = o2;
        float t0v = tg[ob + f], t1v = tg[ob + cs + f], t2v = tg[ob + 2 * cs + f];
        float mx  = fmaxf(o0, fmaxf(o1, o2));
        float lse = mx + __logf(__expf(o0 - mx) + __expf(o1 - mx) + __expf(o2 - mx));
        s += t0v * (lse - o0) + t1v * (lse - o1) + t2v * (lse - o2);
        nz = nz || (t0v != 0.f) || (t1v != 0.f) || (t2v != 0.f);
    }
    if (nz) atomicOr(&mask[bt * 8 + (tid & 7)], 1);

    __shared__ float red[256];
    red[tid] = s;
    __syncthreads();
    for (int o = 128; o > 0; o >>= 1) {
        if (tid < o) red[tid] += red[tid + o];
        __syncthreads();
    }
    if (tid == 0) atomicAdd(accum, (double)red[0]);
}

__global__ void init_kernel(double* accum, int* mask)
{
    if (threadIdx.x == 0) *accum = 0.0;
    if (threadIdx.x < BATCH) mask[threadIdx.x] = 0;
}

__global__ void finalize_kernel(const double* accum, const int* mask,
                                float* out, int out_size)
{
    if (threadIdx.x != 0 || blockIdx.x != 0) return;
    int num = 0;
    for (int i = 0; i < BATCH; i++) num += (mask[i] ? 1 : 0);
    double loss = *accum / ((double)num * (double)NT_OUT);
    if ((unsigned)out_size > OUT_ELEMS) out[OUT_ELEMS] = (float)loss;
}

// ---------------------------------------------------------------------------
// Launch
// ---------------------------------------------------------------------------
static constexpr int conv_smem(int CIN, int COUT, int DIL, int TL, int CHUNK) {
    int halop = ((TL + 4 * DIL + 5) + 3) & ~3;
    int coutp = (COUT + 3) & ~3;
    return (2 * CHUNK * halop + 2 * CHUNK * 10 * coutp + COUT * (TL + 4) + COUT * 2) * 4;
}

extern "C" void kernel_launch(void* const* d_in, const int* in_sizes, int n_in,
                              void* d_out, int out_size)
{
    const float* x  = (const float*)d_in[0];
    const float* tg = (const float*)d_in[1];
    const float *w[5], *g[4], *bb[4], *mm[4], *vv[4], *b_out;

    bool inter = (n_in > 3) && (in_sizes[3] == 64);
    if (inter) {
        for (int i = 0; i < 4; i++) {
            w[i]  = (const float*)d_in[2 + 5 * i];
            g[i]  = (const float*)d_in[3 + 5 * i];
            bb[i] = (const float*)d_in[4 + 5 * i];
            mm[i] = (const float*)d_in[5 + 5 * i];
            vv[i] = (const float*)d_in[6 + 5 * i];
        }
    } else {
        for (int i = 0; i < 4; i++) {
            w[i]  = (const float*)d_in[2 + i];
            g[i]  = (const float*)d_in[6 + i];
            bb[i] = (const float*)d_in[10 + i];
            mm[i] = (const float*)d_in[14 + i];
            vv[i] = (const float*)d_in[18 + i];
        }
    }
    w[4]  = (const float*)d_in[22];
    b_out = (const float*)d_in[23];

    float *bufA, *bufB, *wprep;
    double* accum;
    int* mask;
    cudaGetSymbolAddress((void**)&bufA, g_bufA);
    cudaGetSymbolAddress((void**)&bufB, g_bufB);
    cudaGetSymbolAddress((void**)&wprep, g_wprep);
    cudaGetSymbolAddress((void**)&accum, g_loss_accum);
    cudaGetSymbolAddress((void**)&mask, g_mask);

    // prepped-weight layout offsets (floats): CIN*10*COUTP per layer
    const size_t wo0 = 0;
    const size_t wo1 = wo0 + 128 * 10 * 64;   //  87040 (COUTP=64)
    const size_t wo2 = wo1 + 64 * 10 * 36;    // +23040 (COUTP=36? no: (32+3)&~3=32 -> see below)
    // recompute carefully: COUTP = (COUT+3)&~3 : 64->64, 32->32, 16->16, 8->8, 3->4
    const size_t o0 = 0;
    const size_t o1 = o0 + (size_t)128 * 10 * 64;  //  81920
    const size_t o2 = o1 + (size_t)64 * 10 * 32;   // +20480
    const size_t o3 = o2 + (size_t)32 * 10 * 16;   // +5120
    const size_t o4 = o3 + (size_t)16 * 10 * 8;    // +1280
    // L4 size: 8*10*4 = 320; total = 109120 < 131072

    prep_weights<<<(64 * 128 * 5 + 255) / 256, 256>>>(w[0], wprep + o0, 128, 64, 64, 8);
    prep_weights<<<(32 * 64 * 5 + 255) / 256, 256>>>(w[1], wprep + o1, 64, 32, 32, 8);
    prep_weights<<<(16 * 32 * 5 + 255) / 256, 256>>>(w[2], wprep + o2, 32, 16, 16, 8);
    prep_weights<<<(8 * 16 * 5 + 255) / 256, 256>>>(w[3], wprep + o3, 16, 8, 8, 8);
    prep_weights<<<(3 * 8 * 5 + 255) / 256, 256>>>(w[4], wprep + o4, 8, 3, 4, 8);

    constexpr int SM0 = conv_smem(128, 64, 1, 128, 8);
    constexpr int SM1 = conv_smem(64, 32, 2, 256, 8);
    constexpr int SM2 = conv_smem(32, 16, 4, 512, 8);
    constexpr int SM3 = conv_smem(16, 8, 8, 1024, 8);
    constexpr int SM4 = conv_smem(8, 3, 16, 1024, 8);
    constexpr int SMT = 3 * 8 * TTP * 4;

    cudaFuncSetAttribute(conv_layer<128, 64, 1, 128, 8, 8, true, false>,
                         cudaFuncAttributeMaxDynamicSharedMemorySize, SM0);
    cudaFuncSetAttribute(conv_layer<64, 32, 2, 256, 8, 8, true, false>,
                         cudaFuncAttributeMaxDynamicSharedMemorySize, SM1);
    cudaFuncSetAttribute(conv_layer<32, 16, 4, 512, 8, 8, true, false>,
                         cudaFuncAttributeMaxDynamicSharedMemorySize, SM2);
    cudaFuncSetAttribute(conv_layer<16, 8, 8, 1024, 8, 8, true, false>,
                         cudaFuncAttributeMaxDynamicSharedMemorySize, SM3);
    cudaFuncSetAttribute(conv_layer<8, 3, 16, 1024, 3, 8, false, true>,
                         cudaFuncAttributeMaxDynamicSharedMemorySize, SM4);
    cudaFuncSetAttribute(transpose_loss,
                         cudaFuncAttributeMaxDynamicSharedMemorySize, SMT);

    init_kernel<<<1, 256>>>(accum, mask);

    conv_layer<128, 64, 1, 128, 8, 8, true, false>
        <<<dim3(1024 / 128, BATCH), 256, SM0>>>(x, wprep + o0, g[0], bb[0], mm[0], vv[0],
                                                nullptr, bufA, 1024);
    conv_layer<64, 32, 2, 256, 8, 8, true, false>
        <<<dim3(2048 / 256, BATCH), 256, SM1>>>(bufA, wprep + o1, g[1], bb[1], mm[1], vv[1],
                                                nullptr, bufB, 2048);
    conv_layer<32, 16, 4, 512, 8, 8, true, false>
        <<<dim3(4096 / 512, BATCH), 256, SM2>>>(bufB, wprep + o2, g[2], bb[2], mm[2], vv[2],
                                                nullptr, bufA, 4096);
    conv_layer<16, 8, 8, 1024, 8, 8, true, false>
        <<<dim3(8192 / 1024, BATCH), 256, SM3>>>(bufA, wprep + o3, g[3], bb[3], mm[3], vv[3],
                                                 nullptr, bufB, 8192);
    conv_layer<8, 3, 16, 1024, 3, 8, false, true>
        <<<dim3(16384 / 1024, BATCH), 256, SM4>>>(bufB, wprep + o4, nullptr, nullptr, nullptr,
                                                  nullptr, b_out, bufA, 16384);

    transpose_loss<<<dim3(NT_OUT / TT, 32), 256, SMT>>>(bufA, tg, (float*)d_out,
                                                        accum, mask);
    finalize_kernel<<<1, 1>>>(accum, mask, (float*)d_out, out_size);
}